// round 11
// baseline (speedup 1.0000x reference)
#include <cuda_runtime.h>
#include <cstddef>

#define LSEQ 256
#define NB   8
#define NC   64
#define PTOT 37120   // padded row-layout size (rs(255)+pads < 36700)
#define DPAD 64      // slack for past-row-end reads of discarded lanes

// t = max_c scores, padded-row layout: g_td[b*PTOT + rs(i) + (e-i-1)]
__device__ float g_td[NB * PTOT];

// Bank-aligned row starts, closed form: rs(i) % 32 == i % 32.
// Row i has 255-i cells; pad_i = (i+2)&31.
__host__ __device__ __forceinline__ int rs_pad(int i) {
    const int q = i >> 5, k = i & 31;
    const int g = (k <= 30) ? ((k * (k + 3)) >> 1) : 495;
    return i * 255 - ((i * (i - 1)) >> 1) + 496 * q + g;
}

// ---------------------------------------------------------------------------
// Kernel 1: t[b,i,e] = max over C of scores[b,i,e,:], upper triangle only.
// ---------------------------------------------------------------------------
__global__ void max_kernel(const float* __restrict__ scores) {
    const int i    = blockIdx.x;          // 0 .. 254
    const int b    = blockIdx.y;
    const int warp = threadIdx.x >> 5;
    const int lane = threadIdx.x & 31;
    const int base = b * PTOT + rs_pad(i) - i - 1;

    for (int e = i + 1 + warp; e < LSEQ; e += 8) {
        const float* p = scores + (((size_t)b * LSEQ + i) * LSEQ + e) * NC;
        float v = fmaxf(p[lane], p[lane + 32]);
        #pragma unroll
        for (int o = 16; o > 0; o >>= 1)
            v = fmaxf(v, __shfl_xor_sync(0xffffffffu, v, o));
        if (lane == 0)
            g_td[base + e] = v;
    }
}

// ---------------------------------------------------------------------------
// Kernel 2: CKY inside (max semiring), one 1024-thread CTA per batch.
// Bank-aligned padded-row chart in SMEM (rs(i) ≡ i mod 32 -> every access is
// a bank permutation; right operands for the 4 widths adjacent).
// Per pass (widths w..w+3):
//  Bulk (adaptive j-split): j in [4, w-1], valid for all 4 widths.
//  Pre-combine (1024 thr): reduce group partials AND add old-safe boundary
//    terms j in [d+1, min(3, w-1)] -> VV[d][cell].
//  Serial tail (tid<256, partial barriers): ordered terms only —
//    j in [1, d] (fresh right diag) and j in [w, wd-1] (fresh left diag);
//    pass w==2 handled fully serially (j in [1, wd-1]).
// ---------------------------------------------------------------------------
__global__ __launch_bounds__(1024, 1)
void dp_kernel(const int* __restrict__ lens, float* __restrict__ out) {
    const int b = blockIdx.x;
    extern __shared__ float S[];
    float* D  = S;                          // PTOT + DPAD chart
    float* P0 = S + PTOT + DPAD;            // 4 x 1024 bulk partials
    float* VV = P0 + 4 * 1024;              // 4 x 256 pre-combined
    int*   rs = (int*)(VV + 4 * 256);       // padded row starts (256)
    const float* tb  = g_td + b * PTOT;
    const int    tid = threadIdx.x;

    if (tid < 256) rs[tid] = rs_pad(tid);
    __syncthreads();
    if (tid < 255) D[rs[tid]] = tb[rs[tid]];        // width-1 diagonal
    __syncthreads();

    // Serial-thread state: cached row starts + prefetched t for widths 2..5.
    int   rsc = 0, lim = 0;
    float t0 = 0.f, t1 = 0.f, t2 = 0.f, t3 = 0.f;
    if (tid < 256) {
        rsc = rs[tid];
        lim = rsc + (tid < 254 ? 254 - tid : 0);  // last valid col of row tid
        int i0 = rsc + 1;
        t0 = tb[i0     < lim ? i0     : lim];
        t1 = tb[i0 + 1 < lim ? i0 + 1 : lim];
        t2 = tb[i0 + 2 < lim ? i0 + 2 : lim];
        t3 = tb[i0 + 3 < lim ? i0 + 3 : lim];
    }
    __syncthreads();

    for (int w = 2; w < LSEQ; w += 4) {
        const int n = LSEQ - w;              // cells at base width w
        const int s = (n > 128) ? 8 : (n > 64) ? 7 : (n > 32) ? 6 : 5;
        const int c = tid & ((1 << s) - 1);
        const int g = tid >> s;

        // ---- bulk: j in [4, w-1] for all four widths
        float a0 = -1e30f, a1 = -1e30f, a2 = -1e30f, a3 = -1e30f;
        if (c < n && w > 4) {
            const int m   = w - 4;
            const int jlo = 4 + ((g * m) >> (10 - s));
            const int jhi = 4 + (((g + 1) * m) >> (10 - s));
            if (jlo < jhi) {
                const int lb = rs[c] - 1;        // left: D[lb + j]
                int tp = c + jlo;                // rs-table index
                int rb = w - jlo - 1;            // right col (base width)
                #pragma unroll 4
                for (int j = jlo; j < jhi; ++j) {
                    const float L  = D[lb + j];
                    const int   ra = rs[tp] + rb;
                    a0 = fmaxf(a0, L + D[ra]);
                    a1 = fmaxf(a1, L + D[ra + 1]);
                    a2 = fmaxf(a2, L + D[ra + 2]);
                    a3 = fmaxf(a3, L + D[ra + 3]);
                    ++tp; --rb;
                }
            }
        }
        P0[tid]        = a0;
        P0[1024 + tid] = a1;
        P0[2048 + tid] = a2;
        P0[3072 + tid] = a3;
        __syncthreads();

        // ---- pre-combine: group-partial reduction + old-safe boundary terms
        {
            const int d  = tid >> 8;
            const int cc = tid & 255;
            const int wd = w + d;
            const int G  = 1024 >> s;
            const float* PP = P0 + (d << 10);
            float v = -1e30f;
            if (cc < n) {
                #pragma unroll 4
                for (int k = 0; k < G; ++k)
                    v = fmaxf(v, PP[(k << s) + cc]);
            }
            if (wd <= 255 && cc < LSEQ - wd) {
                const int jmax = (w - 1 < 3) ? w - 1 : 3;   // old-safe bound
                const int rcb  = rs[cc];
                for (int j = d + 1; j <= jmax; ++j)
                    v = fmaxf(v, D[rcb + j - 1] + D[rs[cc + j] + wd - j - 1]);
            }
            VV[(d << 8) + cc] = v;
        }
        __syncthreads();

        // ---- serial tail: ordered terms + store, width by width
        if (tid < 256) {
            #pragma unroll
            for (int d = 0; d < 4; ++d) {
                const int wd = w + d;
                if (wd <= 255 && tid < LSEQ - wd) {
                    float v = VV[(d << 8) + tid];
                    if (w > 2) {
                        // j in [1, d]: left diag old, right diag fresh
                        #pragma unroll
                        for (int j = 1; j <= 3; ++j)
                            if (j <= d)
                                v = fmaxf(v, D[rsc + j - 1] +
                                             D[rs[tid + j] + wd - j - 1]);
                        // j in [w, wd-1]: left diag fresh
                        for (int j = w; j < wd; ++j)
                            v = fmaxf(v, D[rsc + j - 1] +
                                         D[rs[tid + j] + wd - j - 1]);
                    } else {
                        // first pass: everything serial (j in [1, wd-1])
                        for (int j = 1; j < wd; ++j)
                            v = fmaxf(v, D[rsc + j - 1] +
                                         D[rs[tid + j] + wd - j - 1]);
                    }
                    const float tt = (d == 0) ? t0 : (d == 1) ? t1
                                   : (d == 2) ? t2 : t3;
                    D[rsc + wd - 1] = v + tt;
                }
                asm volatile("bar.sync 1, 256;" ::: "memory");
            }
            // prefetch t for next pass (widths w+4..w+7), clamped to row end
            int i0 = rsc + w + 3;
            t0 = tb[i0     < lim ? i0     : lim];
            t1 = tb[i0 + 1 < lim ? i0 + 1 : lim];
            t2 = tb[i0 + 2 < lim ? i0 + 2 : lim];
            t3 = tb[i0 + 3 < lim ? i0 + 3 : lim];
        }
        __syncthreads();
    }

    if (tid == 0) {
        int len = lens[b];
        len = len < 1 ? 1 : (len > 255 ? 255 : len);
        out[b] = D[len - 1];                 // s[0, len] = row 0, col len-1
    }
}

// ---------------------------------------------------------------------------
extern "C" void kernel_launch(void* const* d_in, const int* in_sizes, int n_in,
                              void* d_out, int out_size) {
    const float* scores = (const float*)d_in[0];
    const int*   lens   = (const int*)d_in[1];
    float*       out    = (float*)d_out;
    (void)in_sizes; (void)n_in; (void)out_size;

    const int smem = (PTOT + DPAD + 4 * 1024 + 4 * 256 + 256) * (int)sizeof(float);
    cudaFuncSetAttribute(dp_kernel,
                         cudaFuncAttributeMaxDynamicSharedMemorySize, smem);

    max_kernel<<<dim3(LSEQ - 1, NB), 256>>>(scores);
    dp_kernel<<<NB, 1024, smem>>>(lens, out);
}

// round 12
// speedup vs baseline: 1.6334x; 1.6334x over previous
#include <cuda_runtime.h>
#include <cstddef>

#define LSEQ 256
#define NB   8
#define NC   64
#define PTOT 37120   // padded row-layout size (rs(255) = 36607)
#define DPAD 512     // slack for discarded-lane bulk reads

// t = max_c scores, padded-row layout: g_td[b*PTOT + rs(i) + (e-i-1)]
__device__ float g_td[NB * PTOT];

// Bank-aligned row starts, closed form: rs(i) % 32 == i % 32.
// Row i has 255-i cells; pad_i = (i+2)&31; per-32-block pad sum = 496.
__host__ __device__ __forceinline__ int rs_pad(int i) {
    const int q = i >> 5, k = i & 31;
    const int g = (k <= 30) ? ((k * (k + 3)) >> 1) : 495;
    return i * 255 - ((i * (i - 1)) >> 1) + 496 * q + g;
}

// ---------------------------------------------------------------------------
// Kernel 1: t[b,i,e] = max over C of scores[b,i,e,:], upper triangle only.
// ---------------------------------------------------------------------------
__global__ void max_kernel(const float* __restrict__ scores) {
    const int i    = blockIdx.x;          // 0 .. 254
    const int b    = blockIdx.y;
    const int warp = threadIdx.x >> 5;
    const int lane = threadIdx.x & 31;
    const int base = b * PTOT + rs_pad(i) - i - 1;

    for (int e = i + 1 + warp; e < LSEQ; e += 8) {
        const float* p = scores + (((size_t)b * LSEQ + i) * LSEQ + e) * NC;
        float v = fmaxf(p[lane], p[lane + 32]);
        #pragma unroll
        for (int o = 16; o > 0; o >>= 1)
            v = fmaxf(v, __shfl_xor_sync(0xffffffffu, v, o));
        if (lane == 0)
            g_td[base + e] = v;
    }
}

// ---------------------------------------------------------------------------
// Kernel 2: CKY inside (max semiring), one 1024-thread CTA per batch.
// Identical structure to the R10 winner; only the rs table is now computed
// in closed form (rs_init kernel deleted).
// ---------------------------------------------------------------------------
__global__ __launch_bounds__(1024, 1)
void dp_kernel(const int* __restrict__ lens, float* __restrict__ out) {
    const int b = blockIdx.x;
    extern __shared__ float S[];
    float* D  = S;                          // PTOT + DPAD chart
    float* P0 = S + PTOT + DPAD;            // 4 x 1024 bulk partials
    float* VV = P0 + 4 * 1024;              // 4 x 256 pre-combined
    int*   rs = (int*)(VV + 4 * 256);       // padded row starts
    const float* tb  = g_td + b * PTOT;
    const int    tid = threadIdx.x;

    if (tid < 256) rs[tid] = rs_pad(tid);
    __syncthreads();
    if (tid < 255) D[rs[tid]] = tb[rs[tid]];        // width-1 diagonal
    __syncthreads();

    // Serial-thread state: cached row starts + prefetched t for widths 2..5.
    int   rsc = 0, rs1 = 0, rs2 = 0, rs3 = 0, lim = 0;
    float t0 = 0.f, t1 = 0.f, t2 = 0.f, t3 = 0.f;
    if (tid < 256) {
        rsc = rs[tid];
        rs1 = rs[tid < 255 ? tid + 1 : 255];
        rs2 = rs[tid < 254 ? tid + 2 : 255];
        rs3 = rs[tid < 253 ? tid + 3 : 255];
        lim = rsc + (tid < 254 ? 254 - tid : 0);  // last valid col of row tid
        int i0 = rsc + 1;
        t0 = tb[i0     < lim ? i0     : lim];
        t1 = tb[i0 + 1 < lim ? i0 + 1 : lim];
        t2 = tb[i0 + 2 < lim ? i0 + 2 : lim];
        t3 = tb[i0 + 3 < lim ? i0 + 3 : lim];
    }
    __syncthreads();

    for (int w = 2; w < LSEQ; w += 4) {
        const int n = LSEQ - w;              // cells at base width w
        const int s = (n > 128) ? 8 : (n > 64 ? 7 : 6);
        const int c = tid & ((1 << s) - 1);
        const int g = tid >> s;

        // ---- bulk: j in [4, w-1] for all four widths
        float a0 = -1e30f, a1 = -1e30f, a2 = -1e30f, a3 = -1e30f;
        if (c < n && w > 4) {
            const int m   = w - 4;
            const int jlo = 4 + ((g * m) >> (10 - s));
            const int jhi = 4 + (((g + 1) * m) >> (10 - s));
            if (jlo < jhi) {
                const int lb = rs[c] - 1;        // left: D[lb + j]
                int tp = c + jlo;                // rs-table index
                int rb = w - jlo - 1;            // right col (base width)
                #pragma unroll 4
                for (int j = jlo; j < jhi; ++j) {
                    const float L  = D[lb + j];
                    const int   ra = rs[tp] + rb;
                    a0 = fmaxf(a0, L + D[ra]);
                    a1 = fmaxf(a1, L + D[ra + 1]);
                    a2 = fmaxf(a2, L + D[ra + 2]);
                    a3 = fmaxf(a3, L + D[ra + 3]);
                    ++tp; --rb;
                }
            }
        }
        P0[tid]        = a0;
        P0[1024 + tid] = a1;
        P0[2048 + tid] = a2;
        P0[3072 + tid] = a3;
        __syncthreads();

        // ---- pre-combine: reduce G group-partials per (width d, cell cc)
        {
            const int d  = tid >> 8;
            const int cc = tid & 255;
            const int G  = 1024 >> s;
            const float* PP = P0 + (d << 10);
            float v = -1e30f;
            if (cc < n) {
                #pragma unroll 4
                for (int k = 0; k < G; ++k)
                    v = fmaxf(v, PP[(k << s) + cc]);
            }
            VV[(d << 8) + cc] = v;
        }
        __syncthreads();

        // ---- serial tail: boundary terms + store, width by width
        if (tid < 256) {
            #pragma unroll
            for (int d = 0; d < 4; ++d) {
                const int wd = w + d;
                if (wd <= 255 && tid < LSEQ - wd) {
                    float v = VV[(d << 8) + tid];
                    v = fmaxf(v, D[rsc] + D[rs1 + wd - 2]);                 // j=1
                    if (wd >= 3) v = fmaxf(v, D[rsc + 1] + D[rs2 + wd - 3]); // j=2
                    if (wd >= 4) v = fmaxf(v, D[rsc + 2] + D[rs3 + wd - 4]); // j=3
                    for (int j = (w > 4 ? w : 4); j < wd; ++j)               // high
                        v = fmaxf(v, D[rsc + j - 1] + D[rs[tid + j] + wd - j - 1]);
                    const float tt = (d == 0) ? t0 : (d == 1) ? t1
                                   : (d == 2) ? t2 : t3;
                    D[rsc + wd - 1] = v + tt;
                }
                asm volatile("bar.sync 1, 256;" ::: "memory");
            }
            // prefetch t for next pass (widths w+4..w+7), clamped to row end
            int i0 = rsc + w + 3;
            t0 = tb[i0     < lim ? i0     : lim];
            t1 = tb[i0 + 1 < lim ? i0 + 1 : lim];
            t2 = tb[i0 + 2 < lim ? i0 + 2 : lim];
            t3 = tb[i0 + 3 < lim ? i0 + 3 : lim];
        }
        __syncthreads();
    }

    if (tid == 0) {
        int len = lens[b];
        len = len < 1 ? 1 : (len > 255 ? 255 : len);
        out[b] = D[len - 1];                 // s[0, len] = row 0, col len-1
    }
}

// ---------------------------------------------------------------------------
extern "C" void kernel_launch(void* const* d_in, const int* in_sizes, int n_in,
                              void* d_out, int out_size) {
    const float* scores = (const float*)d_in[0];
    const int*   lens   = (const int*)d_in[1];
    float*       out    = (float*)d_out;
    (void)in_sizes; (void)n_in; (void)out_size;

    const int smem = (PTOT + DPAD + 4 * 1024 + 4 * 256 + 256) * (int)sizeof(float);
    cudaFuncSetAttribute(dp_kernel,
                         cudaFuncAttributeMaxDynamicSharedMemorySize, smem);

    max_kernel<<<dim3(LSEQ - 1, NB), 256>>>(scores);
    dp_kernel<<<NB, 1024, smem>>>(lens, out);
}

// round 13
// speedup vs baseline: 1.6476x; 1.0087x over previous
#include <cuda_runtime.h>
#include <cstdint>

#define LSEQ 256
#define NB   8
#define NC   64
#define PTOT 37120   // padded row-layout size (rs(255) = 36607)
#define DPAD 512     // slack for discarded-lane bulk reads

// t = max_c scores, padded-row layout: g_td[b*PTOT + rs(i) + (e-i-1)]
__device__ float g_td[NB * PTOT];

// Bank-aligned row starts, closed form: rs(i) % 32 == i % 32.
__host__ __device__ __forceinline__ int rs_pad(int i) {
    const int q = i >> 5, k = i & 31;
    const int g = (k <= 30) ? ((k * (k + 3)) >> 1) : 495;
    return i * 255 - ((i * (i - 1)) >> 1) + 496 * q + g;
}

__device__ __forceinline__ uint32_t smem_u32(const void* p) {
    uint32_t a;
    asm("{ .reg .u64 t; cvta.to.shared.u64 t, %1; cvt.u32.u64 %0, t; }"
        : "=r"(a) : "l"(p));
    return a;
}

// ---------------------------------------------------------------------------
// Kernel 1: t[b,i,e] = max over C of scores[b,i,e,:], upper triangle only.
// ---------------------------------------------------------------------------
__global__ void max_kernel(const float* __restrict__ scores) {
    const int i    = blockIdx.x;          // 0 .. 254
    const int b    = blockIdx.y;
    const int warp = threadIdx.x >> 5;
    const int lane = threadIdx.x & 31;
    const int base = b * PTOT + rs_pad(i) - i - 1;

    for (int e = i + 1 + warp; e < LSEQ; e += 8) {
        const float* p = scores + (((size_t)b * LSEQ + i) * LSEQ + e) * NC;
        float v = fmaxf(p[lane], p[lane + 32]);
        #pragma unroll
        for (int o = 16; o > 0; o >>= 1)
            v = fmaxf(v, __shfl_xor_sync(0xffffffffu, v, o));
        if (lane == 0)
            g_td[base + e] = v;
    }
}

// ---------------------------------------------------------------------------
// Kernel 2: CKY inside, 2-CTA cluster per batch. Each CTA keeps a FULL local
// chart and computes HALF the j-split groups; per pass the 4x256 pre-combined
// partials are exchanged via DSMEM (double-buffered mailbox) + one cluster
// barrier; both CTAs run the serial tail redundantly on local data.
// ---------------------------------------------------------------------------
__global__ __launch_bounds__(1024, 1) __cluster_dims__(2, 1, 1)
void dp_kernel(const int* __restrict__ lens, float* __restrict__ out) {
    const int b = blockIdx.y;
    extern __shared__ float S[];
    float* D    = S;                              // PTOT + DPAD chart
    float* P0   = S + PTOT + DPAD;                // 4 x 1024 bulk partials
    float* VV   = P0 + 4 * 1024;                  // 4 x 256 local pre-combined
    float* MAIL = VV + 1024;                      // 2 x (4 x 256) peer mailbox
    int*   rs   = (int*)(MAIL + 2048);            // padded row starts
    const float* tb  = g_td + b * PTOT;
    const int    tid = threadIdx.x;

    uint32_t rank;
    asm("mov.u32 %0, %%cluster_ctarank;" : "=r"(rank));

    // Peer mailbox address for this thread (parity-0 slot); parity adds 4KB.
    uint32_t mail_rem;
    {
        uint32_t loc = smem_u32(S) + (uint32_t)(PTOT + DPAD + 4096 + 1024 + tid) * 4u;
        asm("mapa.shared::cluster.u32 %0, %1, %2;"
            : "=r"(mail_rem) : "r"(loc), "r"(rank ^ 1u));
    }

    if (tid < 256) rs[tid] = rs_pad(tid);
    __syncthreads();
    if (tid < 255) D[rs[tid]] = tb[rs[tid]];      // width-1 diagonal
    __syncthreads();

    // Serial-thread state: cached row start + prefetched t for widths 2..5.
    int   rsc = 0, lim = 0;
    float t0 = 0.f, t1 = 0.f, t2 = 0.f, t3 = 0.f;
    if (tid < 256) {
        rsc = rs[tid];
        lim = rsc + (tid < 254 ? 254 - tid : 0);
        int i0 = rsc + 1;
        t0 = tb[i0     < lim ? i0     : lim];
        t1 = tb[i0 + 1 < lim ? i0 + 1 : lim];
        t2 = tb[i0 + 2 < lim ? i0 + 2 : lim];
        t3 = tb[i0 + 3 < lim ? i0 + 3 : lim];
    }
    __syncthreads();

    int par = 0;
    for (int w = 2; w < LSEQ; w += 4) {
        const int n  = LSEQ - w;             // cells at base width w
        const int sB = (n > 128) ? 8 : (n > 64 ? 7 : 6);
        const int c  = tid & ((1 << sB) - 1);
        const int gl = tid >> sB;                        // local group
        const int gg = ((int)rank << (10 - sB)) + gl;    // global group

        // ---- bulk: half the global j-range [4, w-1], all four widths
        float a0 = -1e30f, a1 = -1e30f, a2 = -1e30f, a3 = -1e30f;
        if (c < n && w > 4) {
            const int m   = w - 4;
            const int jlo = 4 + ((gg * m) >> (11 - sB));
            const int jhi = 4 + (((gg + 1) * m) >> (11 - sB));
            if (jlo < jhi) {
                const int lb = rs[c] - 1;        // left: D[lb + j]
                int tp = c + jlo;                // rs-table index
                int rb = w - jlo - 1;            // right col (base width)
                #pragma unroll 4
                for (int j = jlo; j < jhi; ++j) {
                    const float L  = D[lb + j];
                    const int   ra = rs[tp] + rb;
                    a0 = fmaxf(a0, L + D[ra]);
                    a1 = fmaxf(a1, L + D[ra + 1]);
                    a2 = fmaxf(a2, L + D[ra + 2]);
                    a3 = fmaxf(a3, L + D[ra + 3]);
                    ++tp; --rb;
                }
            }
        }
        P0[tid]        = a0;
        P0[1024 + tid] = a1;
        P0[2048 + tid] = a2;
        P0[3072 + tid] = a3;
        __syncthreads();

        // ---- pre-combine local groups; push result to peer mailbox
        {
            const int d  = tid >> 8;
            const int cc = tid & 255;
            const int G  = 1024 >> sB;           // local group count
            const float* PP = P0 + (d << 10);
            float v = -1e30f;
            if (cc < n) {
                #pragma unroll 4
                for (int k = 0; k < G; ++k)
                    v = fmaxf(v, PP[(k << sB) + cc]);
            }
            VV[tid] = v;                          // tid == (d<<8)+cc
            asm volatile("st.shared::cluster.b32 [%0], %1;"
                         :: "r"(mail_rem + (par ? 4096u : 0u)),
                            "r"(__float_as_uint(v)) : "memory");
        }
        // One cluster barrier: orders remote stores (release/acquire) and
        // doubles as the local pre-combine barrier.
        asm volatile("barrier.cluster.arrive.aligned;" ::: "memory");
        asm volatile("barrier.cluster.wait.aligned;"   ::: "memory");

        // ---- serial tail (redundant in both CTAs): merge + fixups + store
        if (tid < 256) {
            const float* MB = MAIL + (par << 10);
            #pragma unroll
            for (int d = 0; d < 4; ++d) {
                const int wd = w + d;
                if (wd <= 255 && tid < LSEQ - wd) {
                    float v = fmaxf(VV[(d << 8) + tid], MB[(d << 8) + tid]);
                    v = fmaxf(v, D[rsc] + D[rs[tid + 1] + wd - 2]);          // j=1
                    if (wd >= 3)
                        v = fmaxf(v, D[rsc + 1] + D[rs[tid + 2] + wd - 3]);  // j=2
                    if (wd >= 4)
                        v = fmaxf(v, D[rsc + 2] + D[rs[tid + 3] + wd - 4]);  // j=3
                    for (int j = (w > 4 ? w : 4); j < wd; ++j)               // high
                        v = fmaxf(v, D[rsc + j - 1] + D[rs[tid + j] + wd - j - 1]);
                    const float tt = (d == 0) ? t0 : (d == 1) ? t1
                                   : (d == 2) ? t2 : t3;
                    D[rsc + wd - 1] = v + tt;
                }
                asm volatile("bar.sync 1, 256;" ::: "memory");
            }
            // prefetch t for next pass (widths w+4..w+7), clamped to row end
            int i0 = rsc + w + 3;
            t0 = tb[i0     < lim ? i0     : lim];
            t1 = tb[i0 + 1 < lim ? i0 + 1 : lim];
            t2 = tb[i0 + 2 < lim ? i0 + 2 : lim];
            t3 = tb[i0 + 3 < lim ? i0 + 3 : lim];
        }
        par ^= 1;
        __syncthreads();
    }

    if (rank == 0 && tid == 0) {
        int len = lens[b];
        len = len < 1 ? 1 : (len > 255 ? 255 : len);
        out[b] = D[len - 1];                 // s[0, len] = row 0, col len-1
    }
}

// ---------------------------------------------------------------------------
extern "C" void kernel_launch(void* const* d_in, const int* in_sizes, int n_in,
                              void* d_out, int out_size) {
    const float* scores = (const float*)d_in[0];
    const int*   lens   = (const int*)d_in[1];
    float*       out    = (float*)d_out;
    (void)in_sizes; (void)n_in; (void)out_size;

    const int smem = (PTOT + DPAD + 4 * 1024 + 1024 + 2048 + 256)
                     * (int)sizeof(float);
    cudaFuncSetAttribute(dp_kernel,
                         cudaFuncAttributeMaxDynamicSharedMemorySize, smem);

    max_kernel<<<dim3(LSEQ - 1, NB), 256>>>(scores);
    dp_kernel<<<dim3(2, NB), 1024, smem>>>(lens, out);
}